// round 10
// baseline (speedup 1.0000x reference)
#include <cuda_runtime.h>
#include <cstdint>
#include <math.h>

#define HB 1024     // K
#define HM 8192     // M
#define RN 735      // true N
#define RNP 768     // padded N
#define YLD 768
#define NOUT 57
#define OUTPP (NOUT*NOUT)

#define KTILE 32
#define STAGES 3
#define KITERS (HB/KTILE)          // 32
#define TILE_B (128*KTILE*4)       // 16 KB
#define STAGE_B (2*TILE_B)         // 32 KB
#define SMEM_B (STAGES*STAGE_B)    // 96 KB

// Scratch (device globals; no allocation)
__device__ __align__(16) float g_A[RNP*HB];             // 3 MB (k16-permuted, tf32)
__device__ __align__(16) float g_Wp[(size_t)HM*HB];     // 32 MB (k16-permuted, tf32)
__device__ __align__(16) float g_Y[(size_t)HM*YLD];     // 25 MB

// ---------------- helpers ----------------
__device__ __forceinline__ float to_tf32(float x) {
    float r; asm("cvt.rna.tf32.f32 %0, %1;" : "=f"(r) : "f"(x)); return r;
}
__device__ __forceinline__ uint32_t smem_u32(const void* p) {
    uint32_t a;
    asm("{ .reg .u64 t; cvta.to.shared.u64 t, %1; cvt.u32.u64 %0, t; }" : "=r"(a) : "l"(p));
    return a;
}
#define SWZ(o) ((o) ^ (((o) >> 3) & 0x70))
__device__ __forceinline__ void cp_async16(uint32_t dst, const void* src) {
    asm volatile("cp.async.cg.shared.global [%0], [%1], 16;" :: "r"(dst), "l"(src));
}
#define CP_COMMIT() asm volatile("cp.async.commit_group;" ::: "memory")
#define CP_WAIT1()  asm volatile("cp.async.wait_group 1;" ::: "memory")

// 16-wide k-interleave: within each 16-float group, source k -> dst position
// layout = [v0,v4,v8,v12, v1,v5,v9,v13, v2,v6,v10,v14, v3,v7,v11,v15]
__device__ __forceinline__ int permdst16(int k) {
    int c = k & ~15, kk = k & 15;
    return c + (kk & 3) * 4 + (kk >> 2);
}

// ---------------------------------------------------------------------------
// Kernel 1: A[r,h] = (sigmoid(te)+1)*relu(mat), tf32-rounded, k16-permuted.
// ---------------------------------------------------------------------------
__global__ void prep_kernel(const float* __restrict__ mat,
                            const float* __restrict__ te) {
    int idx = blockIdx.x * blockDim.x + threadIdx.x;
    if (idx >= RNP * HB) return;
    int r = idx >> 10;
    int h = idx & 1023;
    float v = 0.0f;
    if (r < RN) {
        int t = r / 49;
        int rem = r % 49;
        int m = rem / 7;
        int n = rem % 7;
        float tev = te[h * 15 + t];
        float s = 1.0f / (1.0f + expf(-tev)) + 1.0f;
        float mv = mat[h * 49 + n * 7 + m];
        v = to_tf32(s * fmaxf(mv, 0.0f));
    }
    g_A[(r << 10) + permdst16(h)] = v;
}

// ---------------------------------------------------------------------------
// Kernel 2: W -> g_Wp, tf32-rounded, k16-permuted. 16 floats per thread.
// ---------------------------------------------------------------------------
__global__ void permw_kernel(const float* __restrict__ W) {
    int gid = blockIdx.x * blockDim.x + threadIdx.x;   // 16-float group
    if (gid >= (HM * HB) / 16) return;
    const float4* src = (const float4*)(W + (size_t)gid * 16);
    float4 q0 = src[0], q1 = src[1], q2 = src[2], q3 = src[3];
    float v0 = to_tf32(q0.x), v1 = to_tf32(q0.y), v2 = to_tf32(q0.z), v3 = to_tf32(q0.w);
    float v4 = to_tf32(q1.x), v5 = to_tf32(q1.y), v6 = to_tf32(q1.z), v7 = to_tf32(q1.w);
    float v8 = to_tf32(q2.x), v9 = to_tf32(q2.y), v10 = to_tf32(q2.z), v11 = to_tf32(q2.w);
    float v12 = to_tf32(q3.x), v13 = to_tf32(q3.y), v14 = to_tf32(q3.z), v15 = to_tf32(q3.w);
    float4* dst = (float4*)(g_Wp + (size_t)gid * 16);
    dst[0] = make_float4(v0, v4, v8, v12);
    dst[1] = make_float4(v1, v5, v9, v13);
    dst[2] = make_float4(v2, v6, v10, v14);
    dst[3] = make_float4(v3, v7, v11, v15);
}

// ---------------------------------------------------------------------------
// Kernel 3: tf32 mma.sync GEMM — 3 stages, 2 CTAs/SM, LDS.128 fragments
// (each 16B load feeds 2 k-steps).
// ---------------------------------------------------------------------------
__global__ void __launch_bounds__(256, 2)
gemm_mma(const float* __restrict__ bias) {
    extern __shared__ char smem[];
    uint32_t sb = smem_u32(smem);

    int tid = threadIdx.x, lane = tid & 31, warp = tid >> 5;
    int g = lane >> 2, tg = lane & 3;
    int wm = warp >> 2, wn = warp & 3;          // warp grid 2 (m) x 4 (n)
    int jBase = blockIdx.y * 128;
    int rBase = blockIdx.x * 128;

    const float* wsrc = g_Wp + (size_t)jBase * HB;
    const float* asrc = g_A + (size_t)rBase * HB;
    int lrow = tid >> 1, lhalf = tid & 1;

    float acc[4][4][4];
    #pragma unroll
    for (int mt = 0; mt < 4; mt++)
        #pragma unroll
        for (int nt = 0; nt < 4; nt++)
            #pragma unroll
            for (int i = 0; i < 4; i++) acc[mt][nt][i] = 0.f;

    auto load_stage = [&](int it) {
        int s = it % STAGES;
        int k0 = it * KTILE;
        uint32_t wd = sb + s * STAGE_B;
        uint32_t ad = wd + TILE_B;
        const float* wp = wsrc + (size_t)lrow * HB + k0 + lhalf * 16;
        const float* ap = asrc + (size_t)lrow * HB + k0 + lhalf * 16;
        #pragma unroll
        for (int c = 0; c < 4; c++) {
            uint32_t off = SWZ((uint32_t)(lrow * 128 + lhalf * 64 + c * 16));
            cp_async16(wd + off, wp + c * 4);
            cp_async16(ad + off, ap + c * 4);
        }
    };

    load_stage(0); CP_COMMIT();
    load_stage(1); CP_COMMIT();

    for (int it = 0; it < KITERS; it++) {
        CP_WAIT1();
        __syncthreads();
        int s = it % STAGES;
        const char* wb = smem + s * STAGE_B;
        const char* ab = wb + TILE_B;

        #pragma unroll
        for (int P = 0; P < 2; P++) {          // each P covers ks = 2P, 2P+1
            float4 alo[4], ahi[4], bf[4];
            #pragma unroll
            for (int mt = 0; mt < 4; mt++) {
                int r0 = wm * 64 + mt * 16 + g;
                alo[mt] = *(const float4*)(wb + SWZ((uint32_t)(r0 * 128 + P * 64 + tg * 16)));
                ahi[mt] = *(const float4*)(wb + SWZ((uint32_t)((r0 + 8) * 128 + P * 64 + tg * 16)));
            }
            #pragma unroll
            for (int nt = 0; nt < 4; nt++) {
                int rn_ = wn * 32 + nt * 8 + g;
                bf[nt] = *(const float4*)(ab + SWZ((uint32_t)(rn_ * 128 + P * 64 + tg * 16)));
            }
            #pragma unroll
            for (int e = 0; e < 2; e++) {      // ks = 2P + e
                #pragma unroll
                for (int nt = 0; nt < 4; nt++) {
                    uint32_t b0 = __float_as_uint(e ? bf[nt].z : bf[nt].x);
                    uint32_t b1 = __float_as_uint(e ? bf[nt].w : bf[nt].y);
                    #pragma unroll
                    for (int mt = 0; mt < 4; mt++) {
                        uint32_t a0 = __float_as_uint(e ? alo[mt].z : alo[mt].x);
                        uint32_t a2 = __float_as_uint(e ? alo[mt].w : alo[mt].y);
                        uint32_t a1 = __float_as_uint(e ? ahi[mt].z : ahi[mt].x);
                        uint32_t a3 = __float_as_uint(e ? ahi[mt].w : ahi[mt].y);
                        asm volatile(
                            "mma.sync.aligned.m16n8k8.row.col.f32.tf32.tf32.f32 "
                            "{%0,%1,%2,%3}, {%4,%5,%6,%7}, {%8,%9}, {%0,%1,%2,%3};"
                            : "+f"(acc[mt][nt][0]), "+f"(acc[mt][nt][1]),
                              "+f"(acc[mt][nt][2]), "+f"(acc[mt][nt][3])
                            : "r"(a0), "r"(a1), "r"(a2), "r"(a3),
                              "r"(b0), "r"(b1));
                    }
                }
            }
        }
        __syncthreads();
        if (it + 2 < KITERS) { load_stage(it + 2); CP_COMMIT(); }
    }

    // epilogue: bias + relu
    #pragma unroll
    for (int mt = 0; mt < 4; mt++) {
        int r0 = jBase + wm * 64 + mt * 16 + g;
        float bv0 = bias[r0], bv1 = bias[r0 + 8];
        float* y0 = g_Y + (size_t)r0 * YLD + rBase + wn * 32;
        float* y1 = g_Y + (size_t)(r0 + 8) * YLD + rBase + wn * 32;
        #pragma unroll
        for (int nt = 0; nt < 4; nt++) {
            float2 v0, v1;
            v0.x = fmaxf(acc[mt][nt][0] + bv0, 0.f);
            v0.y = fmaxf(acc[mt][nt][1] + bv0, 0.f);
            v1.x = fmaxf(acc[mt][nt][2] + bv1, 0.f);
            v1.y = fmaxf(acc[mt][nt][3] + bv1, 0.f);
            *(float2*)(y0 + nt * 8 + tg * 2) = v0;
            *(float2*)(y1 + nt * 8 + tg * 2) = v1;
        }
    }
}

// ---------------------------------------------------------------------------
// Kernel 4: assemble + normalize; warp-per-row, stride-7 gathers (R7 proven).
// ---------------------------------------------------------------------------
__global__ void __launch_bounds__(256)
assemble_kernel(float* __restrict__ out) {
    int j = blockIdx.x;
    __shared__ float ys[RN];
    __shared__ float dsh[NOUT];
    int tid = threadIdx.x;
    int warp = tid >> 5, lane = tid & 31;

    const float* yrow = &g_Y[(size_t)j * YLD];
    for (int i = tid; i < RN; i += 256) ys[i] = yrow[i];
    __syncthreads();

    if (tid < NOUT) {
        float sum;
        if (tid == 0) {
            sum = 9.0f;
        } else {
            int rr = tid - 1;
            int s = rr / 7;
            int q = rr - s * 7;
            sum = (q == 6) ? 1.0f : 0.0f;
            int pbase = 7 * (7 - s);
            #pragma unroll 8
            for (int k = 0; k < 56; k++)
                sum += ys[(pbase + k) * 7 + q];
        }
        dsh[tid] = rsqrtf(fmaxf(sum, 1.0f));
    }
    __syncthreads();

    float* o = out + (size_t)j * OUTPP;
    #pragma unroll
    for (int r = warp; r < NOUT; r += 8) {
        float dr = dsh[r];
        if (r == 0) {
            #pragma unroll
            for (int c = lane; c < NOUT; c += 32) {
                int cd7 = (c * 37) >> 8;          // c/7 for c<=56
                float v = (c - cd7 * 7 == 0) ? dr * dsh[c] : 0.f;
                o[c] = v;
            }
        } else {
            int rr = r - 1;
            int s = (rr * 37) >> 8;               // (r-1)/7
            int q = rr - s * 7;
            int sbase = 49 * (7 - s) + q;         // src(c) = sbase + 7*(c-1)
            #pragma unroll
            for (int c = lane; c < NOUT; c += 32) {
                float v;
                if (c == 0) v = (q == 6) ? 1.0f : 0.0f;
                else        v = ys[sbase + 7 * (c - 1)];
                o[r * NOUT + c] = v * dr * dsh[c];
            }
        }
    }
}

// ---------------------------------------------------------------------------
extern "C" void kernel_launch(void* const* d_in, const int* in_sizes, int n_in,
                              void* d_out, int out_size) {
    const float* mat = (const float*)d_in[0];
    const float* te  = (const float*)d_in[1];
    const float* W   = (const float*)d_in[2];
    const float* b   = (const float*)d_in[3];
    float* out = (float*)d_out;

    static bool attr_set = false;
    if (!attr_set) {
        cudaFuncSetAttribute(gemm_mma, cudaFuncAttributeMaxDynamicSharedMemorySize,
                             SMEM_B);
        attr_set = true;
    }

    prep_kernel<<<(RNP * HB + 255) / 256, 256>>>(mat, te);
    permw_kernel<<<(HM * HB / 16 + 255) / 256, 256>>>(W);

    dim3 g(RNP / 128, HM / 128);   // (6, 64)
    gemm_mma<<<g, 256, SMEM_B>>>(b);

    assemble_kernel<<<HM, 256>>>(out);
}

// round 11
// speedup vs baseline: 1.2656x; 1.2656x over previous
#include <cuda_runtime.h>
#include <cstdint>
#include <math.h>

#define HB 1024     // K
#define HM 8192     // M
#define RN 735      // true N
#define RNP 768     // padded N
#define YLD 768
#define NOUT 57
#define OUTPP (NOUT*NOUT)

#define KTILE 32
#define STAGES 3
#define KITERS (HB/KTILE)          // 32
#define TILE_B (128*KTILE*4)       // 16 KB
#define STAGE_B (2*TILE_B)         // 32 KB
#define SMEM_B (STAGES*STAGE_B)    // 96 KB

// Scratch (device globals; no allocation)
__device__ __align__(16) float g_A[RNP*HB];             // 3 MB (k16-permuted+rot, tf32)
__device__ __align__(16) float g_Wp[(size_t)HM*HB];     // 32 MB (k16-permuted+rot, tf32)
__device__ __align__(16) float g_Y[(size_t)HM*YLD];     // 25 MB

// ---------------- helpers ----------------
__device__ __forceinline__ float to_tf32(float x) {
    float r; asm("cvt.rna.tf32.f32 %0, %1;" : "=f"(r) : "f"(x)); return r;
}
__device__ __forceinline__ uint32_t smem_u32(const void* p) {
    uint32_t a;
    asm("{ .reg .u64 t; cvta.to.shared.u64 t, %1; cvt.u32.u64 %0, t; }" : "=r"(a) : "l"(p));
    return a;
}
__device__ __forceinline__ void cp_async16(uint32_t dst, const void* src) {
    asm volatile("cp.async.cg.shared.global [%0], [%1], 16;" :: "r"(dst), "l"(src));
}
#define CP_COMMIT() asm volatile("cp.async.commit_group;" ::: "memory")
#define CP_WAIT1()  asm volatile("cp.async.wait_group 1;" ::: "memory")

// 16-wide k-interleave within each 16-float group:
// layout = [v0,v4,v8,v12, v1,v5,v9,v13, v2,v6,v10,v14, v3,v7,v11,v15]
__device__ __forceinline__ int permdst16(int k) {
    int c = k & ~15, kk = k & 15;
    return c + (kk & 3) * 4 + (kk >> 2);
}

// ---------------------------------------------------------------------------
// Kernel 1: A[r,h] = (sigmoid(te)+1)*relu(mat), tf32-rounded, k16-permuted,
// odd rows: 64B-half-swap within each 128B window (conflict-free frags).
// ---------------------------------------------------------------------------
__global__ void prep_kernel(const float* __restrict__ mat,
                            const float* __restrict__ te) {
    int idx = blockIdx.x * blockDim.x + threadIdx.x;
    if (idx >= RNP * HB) return;
    int r = idx >> 10;
    int h = idx & 1023;
    float v = 0.0f;
    if (r < RN) {
        int t = r / 49;
        int rem = r % 49;
        int m = rem / 7;
        int n = rem % 7;
        float tev = te[h * 15 + t];
        float s = 1.0f / (1.0f + expf(-tev)) + 1.0f;
        float mv = mat[h * 49 + n * 7 + m];
        v = to_tf32(s * fmaxf(mv, 0.0f));
    }
    int dst = permdst16(h) ^ ((r & 1) << 4);   // odd row: flip 16-float half
    g_A[(r << 10) + dst] = v;
}

// ---------------------------------------------------------------------------
// Kernel 2: W -> g_Wp, tf32-rounded, k16-permuted, odd-row half-swap.
// ---------------------------------------------------------------------------
__global__ void permw_kernel(const float* __restrict__ W) {
    int gid = blockIdx.x * blockDim.x + threadIdx.x;   // 16-float group
    if (gid >= (HM * HB) / 16) return;
    int row = gid >> 6;                                // 64 groups per row
    const float4* src = (const float4*)(W + (size_t)gid * 16);
    float4 q0 = src[0], q1 = src[1], q2 = src[2], q3 = src[3];
    float v0 = to_tf32(q0.x), v1 = to_tf32(q0.y), v2 = to_tf32(q0.z), v3 = to_tf32(q0.w);
    float v4 = to_tf32(q1.x), v5 = to_tf32(q1.y), v6 = to_tf32(q1.z), v7 = to_tf32(q1.w);
    float v8 = to_tf32(q2.x), v9 = to_tf32(q2.y), v10 = to_tf32(q2.z), v11 = to_tf32(q2.w);
    float v12 = to_tf32(q3.x), v13 = to_tf32(q3.y), v14 = to_tf32(q3.z), v15 = to_tf32(q3.w);
    size_t dbase = ((size_t)gid * 16) ^ (size_t)((row & 1) << 4);
    float4* dst = (float4*)(g_Wp + dbase);
    dst[0] = make_float4(v0, v4, v8, v12);
    dst[1] = make_float4(v1, v5, v9, v13);
    dst[2] = make_float4(v2, v6, v10, v14);
    dst[3] = make_float4(v3, v7, v11, v15);
}

// ---------------------------------------------------------------------------
// Kernel 3: tf32 mma.sync GEMM — 3 stages, 2 CTAs/SM, conflict-free LDS.128
// fragment loads (rotation baked into gmem; cp.async copies linearly).
// ---------------------------------------------------------------------------
__global__ void __launch_bounds__(256, 2)
gemm_mma(const float* __restrict__ bias) {
    extern __shared__ char smem[];
    uint32_t sb = smem_u32(smem);

    int tid = threadIdx.x, lane = tid & 31, warp = tid >> 5;
    int g = lane >> 2, tg = lane & 3;
    int wm = warp >> 2, wn = warp & 3;          // warp grid 2 (m) x 4 (n)
    int jBase = blockIdx.y * 128;
    int rBase = blockIdx.x * 128;

    const float* wsrc = g_Wp + (size_t)jBase * HB;
    const float* asrc = g_A + (size_t)rBase * HB;
    int lrow = tid >> 1, lhalf = tid & 1;
    uint32_t flip = (uint32_t)((g & 1) << 6);   // odd fragment row: ^64 bytes

    float acc[4][4][4];
    #pragma unroll
    for (int mt = 0; mt < 4; mt++)
        #pragma unroll
        for (int nt = 0; nt < 4; nt++)
            #pragma unroll
            for (int i = 0; i < 4; i++) acc[mt][nt][i] = 0.f;

    auto load_stage = [&](int it) {
        int s = it % STAGES;
        int k0 = it * KTILE;
        uint32_t wd = sb + s * STAGE_B;
        uint32_t ad = wd + TILE_B;
        const float* wp = wsrc + (size_t)lrow * HB + k0 + lhalf * 16;
        const float* ap = asrc + (size_t)lrow * HB + k0 + lhalf * 16;
        #pragma unroll
        for (int c = 0; c < 4; c++) {
            uint32_t off = (uint32_t)(lrow * 128 + lhalf * 64 + c * 16);  // linear
            cp_async16(wd + off, wp + c * 4);
            cp_async16(ad + off, ap + c * 4);
        }
    };

    load_stage(0); CP_COMMIT();
    load_stage(1); CP_COMMIT();

    for (int it = 0; it < KITERS; it++) {
        CP_WAIT1();
        __syncthreads();
        int s = it % STAGES;
        const char* wb = smem + s * STAGE_B;
        const char* ab = wb + TILE_B;

        #pragma unroll
        for (int P = 0; P < 2; P++) {          // each P covers ks = 2P, 2P+1
            float4 alo[4], ahi[4], bf[4];
            uint32_t coff = (uint32_t)(P * 64 + tg * 16) ^ flip;
            #pragma unroll
            for (int mt = 0; mt < 4; mt++) {
                int r0 = wm * 64 + mt * 16 + g;
                alo[mt] = *(const float4*)(wb + (uint32_t)(r0 * 128) + coff);
                ahi[mt] = *(const float4*)(wb + (uint32_t)((r0 + 8) * 128) + coff);
            }
            #pragma unroll
            for (int nt = 0; nt < 4; nt++) {
                int rn_ = wn * 32 + nt * 8 + g;
                bf[nt] = *(const float4*)(ab + (uint32_t)(rn_ * 128) + coff);
            }
            #pragma unroll
            for (int e = 0; e < 2; e++) {      // ks = 2P + e
                #pragma unroll
                for (int nt = 0; nt < 4; nt++) {
                    uint32_t b0 = __float_as_uint(e ? bf[nt].z : bf[nt].x);
                    uint32_t b1 = __float_as_uint(e ? bf[nt].w : bf[nt].y);
                    #pragma unroll
                    for (int mt = 0; mt < 4; mt++) {
                        uint32_t a0 = __float_as_uint(e ? alo[mt].z : alo[mt].x);
                        uint32_t a2 = __float_as_uint(e ? alo[mt].w : alo[mt].y);
                        uint32_t a1 = __float_as_uint(e ? ahi[mt].z : ahi[mt].x);
                        uint32_t a3 = __float_as_uint(e ? ahi[mt].w : ahi[mt].y);
                        asm volatile(
                            "mma.sync.aligned.m16n8k8.row.col.f32.tf32.tf32.f32 "
                            "{%0,%1,%2,%3}, {%4,%5,%6,%7}, {%8,%9}, {%0,%1,%2,%3};"
                            : "+f"(acc[mt][nt][0]), "+f"(acc[mt][nt][1]),
                              "+f"(acc[mt][nt][2]), "+f"(acc[mt][nt][3])
                            : "r"(a0), "r"(a1), "r"(a2), "r"(a3),
                              "r"(b0), "r"(b1));
                    }
                }
            }
        }
        __syncthreads();
        if (it + 2 < KITERS) { load_stage(it + 2); CP_COMMIT(); }
    }

    // epilogue: bias + relu
    #pragma unroll
    for (int mt = 0; mt < 4; mt++) {
        int r0 = jBase + wm * 64 + mt * 16 + g;
        float bv0 = bias[r0], bv1 = bias[r0 + 8];
        float* y0 = g_Y + (size_t)r0 * YLD + rBase + wn * 32;
        float* y1 = g_Y + (size_t)(r0 + 8) * YLD + rBase + wn * 32;
        #pragma unroll
        for (int nt = 0; nt < 4; nt++) {
            float2 v0, v1;
            v0.x = fmaxf(acc[mt][nt][0] + bv0, 0.f);
            v0.y = fmaxf(acc[mt][nt][1] + bv0, 0.f);
            v1.x = fmaxf(acc[mt][nt][2] + bv1, 0.f);
            v1.y = fmaxf(acc[mt][nt][3] + bv1, 0.f);
            *(float2*)(y0 + nt * 8 + tg * 2) = v0;
            *(float2*)(y1 + nt * 8 + tg * 2) = v1;
        }
    }
}

// ---------------------------------------------------------------------------
// Kernel 4: assemble + normalize; warp-per-row, stride-7 gathers (proven).
// ---------------------------------------------------------------------------
__global__ void __launch_bounds__(256)
assemble_kernel(float* __restrict__ out) {
    int j = blockIdx.x;
    __shared__ float ys[RN];
    __shared__ float dsh[NOUT];
    int tid = threadIdx.x;
    int warp = tid >> 5, lane = tid & 31;

    const float* yrow = &g_Y[(size_t)j * YLD];
    for (int i = tid; i < RN; i += 256) ys[i] = yrow[i];
    __syncthreads();

    if (tid < NOUT) {
        float sum;
        if (tid == 0) {
            sum = 9.0f;
        } else {
            int rr = tid - 1;
            int s = rr / 7;
            int q = rr - s * 7;
            sum = (q == 6) ? 1.0f : 0.0f;
            int pbase = 7 * (7 - s);
            #pragma unroll 8
            for (int k = 0; k < 56; k++)
                sum += ys[(pbase + k) * 7 + q];
        }
        dsh[tid] = rsqrtf(fmaxf(sum, 1.0f));
    }
    __syncthreads();

    float* o = out + (size_t)j * OUTPP;
    #pragma unroll
    for (int r = warp; r < NOUT; r += 8) {
        float dr = dsh[r];
        if (r == 0) {
            #pragma unroll
            for (int c = lane; c < NOUT; c += 32) {
                int cd7 = (c * 37) >> 8;          // c/7 for c<=56
                float v = (c - cd7 * 7 == 0) ? dr * dsh[c] : 0.f;
                o[c] = v;
            }
        } else {
            int rr = r - 1;
            int s = (rr * 37) >> 8;               // (r-1)/7
            int q = rr - s * 7;
            int sbase = 49 * (7 - s) + q;         // src(c) = sbase + 7*(c-1)
            #pragma unroll
            for (int c = lane; c < NOUT; c += 32) {
                float v;
                if (c == 0) v = (q == 6) ? 1.0f : 0.0f;
                else        v = ys[sbase + 7 * (c - 1)];
                o[r * NOUT + c] = v * dr * dsh[c];
            }
        }
    }
}

// ---------------------------------------------------------------------------
extern "C" void kernel_launch(void* const* d_in, const int* in_sizes, int n_in,
                              void* d_out, int out_size) {
    const float* mat = (const float*)d_in[0];
    const float* te  = (const float*)d_in[1];
    const float* W   = (const float*)d_in[2];
    const float* b   = (const float*)d_in[3];
    float* out = (float*)d_out;

    static bool attr_set = false;
    if (!attr_set) {
        cudaFuncSetAttribute(gemm_mma, cudaFuncAttributeMaxDynamicSharedMemorySize,
                             SMEM_B);
        attr_set = true;
    }

    prep_kernel<<<(RNP * HB + 255) / 256, 256>>>(mat, te);
    permw_kernel<<<(HM * HB / 16 + 255) / 256, 256>>>(W);

    dim3 g(RNP / 128, HM / 128);   // (6, 64)
    gemm_mma<<<g, 256, SMEM_B>>>(b);

    assemble_kernel<<<HM, 256>>>(out);
}